// round 2
// baseline (speedup 1.0000x reference)
#include <cuda_runtime.h>

#define B_ 512
#define S_ 512
#define T_ 128
#define NEGV (-10000.0f)
#define END_ID 1
#define L2E 1.4426950408889634f
#define LN2 0.6931471805599453f

__device__ float g_diff[B_];
__device__ int g_done = 0;

// ---- fast base-2 transcendentals (single MUFU op each) ----
static __device__ __forceinline__ float ex2(float x) {
    float r; asm("ex2.approx.f32 %0, %1;" : "=f"(r) : "f"(x)); return r;
}
static __device__ __forceinline__ float lg2(float x) {
    float r; asm("lg2.approx.f32 %0, %1;" : "=f"(r) : "f"(x)); return r;
}

// ---- packed f32x2 helpers ----
static __device__ __forceinline__ unsigned long long pack2(float lo, float hi) {
    unsigned long long r;
    asm("mov.b64 %0, {%1, %2};" : "=l"(r) : "r"(__float_as_uint(lo)), "r"(__float_as_uint(hi)));
    return r;
}
static __device__ __forceinline__ float hsum2(unsigned long long v) {
    unsigned int lo, hi;
    asm("mov.b64 {%0, %1}, %2;" : "=r"(lo), "=r"(hi) : "l"(v));
    return __uint_as_float(lo) + __uint_as_float(hi);
}
#define FMA2(acc, e, a) asm("fma.rn.f32x2 %0, %1, %2, %0;" : "+l"(acc) : "l"(e), "l"(a))
#define ADD2(o, a, b)   asm("add.rn.f32x2 %0, %1, %2;" : "=l"(o) : "l"(a), "l"(b))

static __device__ __forceinline__ float warp_sum(float v) {
#pragma unroll
    for (int o = 16; o; o >>= 1) v += __shfl_xor_sync(0xffffffffu, v, o);
    return v;
}
static __device__ __forceinline__ float warp_max(float v) {
#pragma unroll
    for (int o = 16; o; o >>= 1) v = fmaxf(v, __shfl_xor_sync(0xffffffffu, v, o));
    return v;
}

// 256 threads: pair (2k, 2k+1) owns tag k; each half does 64 of the 128-wide dot.
__global__ void __launch_bounds__(256, 2) crf_kernel(
    const float* __restrict__ x,      // [B,S,T]
    const int*   __restrict__ tags,   // [B,S]
    const float* __restrict__ mask,   // [B,S]
    const float* __restrict__ trans,  // [T,T]
    float* __restrict__ out)
{
    const int b    = blockIdx.x;
    const int tid  = threadIdx.x;
    const int tag  = tid >> 1;
    const int h    = tid & 1;
    const int lane = tid & 31;
    const int w    = tid >> 5;   // 8 warps

    __shared__ __align__(16) float sa[2][T_];
    __shared__ float s_m[2];
    __shared__ float s_red[8];
    __shared__ int   s_len;
    __shared__ int   s_last;

    // ---- sequence length = sum(mask[b,:]) (contiguous prefix) ----
    float lm = mask[b * S_ + tid] + mask[b * S_ + tid + 256];
    lm = warp_sum(lm);
    if (lane == 0) s_red[w] = lm;
    __syncthreads();
    if (tid == 0) {
        float t = 0.f;
#pragma unroll
        for (int k = 0; k < 8; k++) t += s_red[k];
        s_len = (int)(t + 0.5f);
    }

    // ---- E regs: exp(trans[tag, h*64 .. h*64+63]) as 32 packed f32x2 ----
    unsigned long long er[32];
    {
        const float4* tr4 = reinterpret_cast<const float4*>(trans + tag * T_ + h * 64);
#pragma unroll
        for (int j = 0; j < 16; j++) {
            float4 v = __ldg(tr4 + j);
            er[2 * j]     = pack2(expf(v.x), expf(v.y));
            er[2 * j + 1] = pack2(expf(v.z), expf(v.w));
        }
    }
    __syncthreads();
    const int len = s_len;

    // ---- forward recurrence in base-2, lagged renorm, single barrier/step ----
    float beta = (tag == 0) ? 0.f : NEGV * L2E;   // START_ID = 0
    float mb   = 0.f;                              // renorm = beta_{t-1}[0]
    const float* xb = x + (size_t)b * S_ * T_;
    float xl = xb[tag] * L2E;                      // prefetched x_t * log2(e)
    int p = 0;
    for (int t = 0; t < len; t++) {
        float e = ex2(beta - mb);
        if (h == 0)   sa[p][tag] = e;
        if (tid == 0) s_m[p] = beta;               // broadcast beta_t[0] (lagged m)
        __syncthreads();
        float mb_next = s_m[p];
        float xn = (t + 1 < len) ? xb[(size_t)(t + 1) * T_ + tag] : 0.f;

        const ulonglong2* sp2 =
            reinterpret_cast<const ulonglong2*>(&sa[p][h * 64]);
        unsigned long long a0 = 0ull, a1 = 0ull, a2 = 0ull, a3 = 0ull;
#pragma unroll
        for (int j = 0; j < 16; j += 2) {
            ulonglong2 v0 = sp2[j];
            ulonglong2 v1 = sp2[j + 1];
            FMA2(a0, er[2 * j],     v0.x);
            FMA2(a1, er[2 * j + 1], v0.y);
            FMA2(a2, er[2 * j + 2], v1.x);
            FMA2(a3, er[2 * j + 3], v1.y);
        }
        unsigned long long s01, s23, s;
        ADD2(s01, a0, a1); ADD2(s23, a2, a3); ADD2(s, s01, s23);
        float part = hsum2(s);
        part += __shfl_xor_sync(0xffffffffu, part, 1);  // pair combine, no barrier

        beta = xl + mb + lg2(part);   // consistent: sa was built with mb
        mb = mb_next;
        xl = xn * L2E;
        p ^= 1;
    }

    // ---- fwd = LSE_i(beta_i + trans[END,i]*L2E), base-2 ----
    float v = (h == 0) ? (beta + __ldg(trans + END_ID * T_ + tag) * L2E) : -3.0e38f;
    float mx = warp_max(v);
    __syncthreads();
    if (lane == 0) s_red[w] = mx;
    __syncthreads();
    mx = s_red[0];
#pragma unroll
    for (int k = 1; k < 8; k++) mx = fmaxf(mx, s_red[k]);
    float e2 = (h == 0) ? ex2(v - mx) : 0.f;
    float se = warp_sum(e2);
    __syncthreads();
    if (lane == 0) s_red[w] = se;
    __syncthreads();
    float tot = 0.f;
#pragma unroll
    for (int k = 0; k < 8; k++) tot += s_red[k];
    float fwd = (mx + lg2(tot)) * LN2;

    // ---- gold path score ----
    const int* tb = tags + b * S_;
    float gs = 0.f;
    for (int u = tid; u < len; u += 256) {
        int tn = tb[u + 1];
        int tc = tb[u];
        gs += xb[(size_t)u * T_ + tn] + __ldg(trans + tn * T_ + tc);
    }
    gs = warp_sum(gs);
    __syncthreads();
    if (lane == 0) s_red[w] = gs;
    __syncthreads();
    if (tid == 0) {
        float gtot = 0.f;
#pragma unroll
        for (int k = 0; k < 8; k++) gtot += s_red[k];
        gtot += __ldg(trans + END_ID * T_ + tb[len]);
        g_diff[b] = fwd - gtot;
    }

    // ---- fused finalize: last CTA computes the mean ----
    __syncthreads();
    if (tid == 0) {
        __threadfence();
        int vdone = atomicAdd(&g_done, 1);
        s_last = (vdone == (int)gridDim.x - 1);
    }
    __syncthreads();
    if (s_last) {
        __threadfence();
        float tsum = g_diff[tid] + g_diff[tid + 256];
        tsum = warp_sum(tsum);
        __syncthreads();
        if (lane == 0) s_red[w] = tsum;
        __syncthreads();
        if (tid == 0) {
            float total = 0.f;
#pragma unroll
            for (int k = 0; k < 8; k++) total += s_red[k];
            out[0] = total * (1.0f / B_);
            g_done = 0;   // reset for next graph replay
        }
    }
}

extern "C" void kernel_launch(void* const* d_in, const int* in_sizes, int n_in,
                              void* d_out, int out_size) {
    const float* x     = (const float*)d_in[0];
    const int*   tags  = (const int*)d_in[1];
    const float* mask  = (const float*)d_in[2];
    const float* trans = (const float*)d_in[3];
    crf_kernel<<<B_, 256>>>(x, tags, mask, trans, (float*)d_out);
}

// round 3
// speedup vs baseline: 1.0329x; 1.0329x over previous
#include <cuda_runtime.h>

#define B_ 512
#define S_ 512
#define T_ 128
#define NEGV (-10000.0f)
#define END_ID 1
#define L2E 1.4426950408889634f
#define LN2 0.6931471805599453f
#define PFD 8   // x prefetch depth

__device__ float g_diff[B_];
__device__ int g_done = 0;

static __device__ __forceinline__ float ex2(float x) {
    float r; asm("ex2.approx.f32 %0, %1;" : "=f"(r) : "f"(x)); return r;
}
static __device__ __forceinline__ float lg2(float x) {
    float r; asm("lg2.approx.f32 %0, %1;" : "=f"(r) : "f"(x)); return r;
}
static __device__ __forceinline__ unsigned long long pack2(float lo, float hi) {
    unsigned long long r;
    asm("mov.b64 %0, {%1, %2};" : "=l"(r) : "r"(__float_as_uint(lo)), "r"(__float_as_uint(hi)));
    return r;
}
static __device__ __forceinline__ float hsum2(unsigned long long v) {
    unsigned int lo, hi;
    asm("mov.b64 {%0, %1}, %2;" : "=r"(lo), "=r"(hi) : "l"(v));
    return __uint_as_float(lo) + __uint_as_float(hi);
}
#define FMA2(acc, e, a) asm("fma.rn.f32x2 %0, %1, %2, %0;" : "+l"(acc) : "l"(e), "l"(a))
#define ADD2(o, a, b)   asm("add.rn.f32x2 %0, %1, %2;" : "=l"(o) : "l"(a), "l"(b))

static __device__ __forceinline__ float warp_sum(float v) {
#pragma unroll
    for (int o = 16; o; o >>= 1) v += __shfl_xor_sync(0xffffffffu, v, o);
    return v;
}
static __device__ __forceinline__ float warp_max(float v) {
#pragma unroll
    for (int o = 16; o; o >>= 1) v = fmaxf(v, __shfl_xor_sync(0xffffffffu, v, o));
    return v;
}

// 256 threads: pair (2k,2k+1) owns tag k; each half does 64 of the 128-wide dot.
__global__ void __launch_bounds__(256, 2) crf_kernel(
    const float* __restrict__ x,      // [B,S,T]
    const int*   __restrict__ tags,   // [B,S]
    const float* __restrict__ mask,   // [B,S]
    const float* __restrict__ trans,  // [T,T]
    float* __restrict__ out)
{
    const int b    = blockIdx.x;
    const int tid  = threadIdx.x;
    const int tag  = tid >> 1;
    const int h    = tid & 1;
    const int lane = tid & 31;
    const int w    = tid >> 5;

    __shared__ __align__(16) float sa[2][T_];
    __shared__ float s_m[2];
    __shared__ float s_red[8];
    __shared__ int   s_len;
    __shared__ int   s_last;

    // ---- sequence length (mask is a contiguous prefix) ----
    float lm = mask[b * S_ + tid] + mask[b * S_ + tid + 256];
    lm = warp_sum(lm);
    if (lane == 0) s_red[w] = lm;
    __syncthreads();
    if (tid == 0) {
        float t = 0.f;
#pragma unroll
        for (int k = 0; k < 8; k++) t += s_red[k];
        s_len = (int)(t + 0.5f);
    }

    // ---- E regs: exp(trans[tag, h*64 .. h*64+63]) as 32 packed f32x2 ----
    unsigned long long er[32];
    {
        const float4* tr4 = reinterpret_cast<const float4*>(trans + tag * T_ + h * 64);
#pragma unroll
        for (int j = 0; j < 16; j++) {
            float4 v = __ldg(tr4 + j);
            er[2 * j]     = pack2(ex2(v.x * L2E), ex2(v.y * L2E));
            er[2 * j + 1] = pack2(ex2(v.z * L2E), ex2(v.w * L2E));
        }
    }
    __syncthreads();
    const int len = s_len;
    const float* xb = x + (size_t)b * S_ * T_;

    // ---- deep x prefetch ring ----
    float xr[PFD];
#pragma unroll
    for (int d = 0; d < PFD; d++)
        xr[d] = __ldg(xb + (size_t)min(d, len - 1) * T_ + tag) * L2E;

    // ---- forward recurrence: base-2, lagged renorm, single barrier/step ----
    float beta = (tag == 0) ? 0.f : NEGV * L2E;   // START_ID = 0
    float mb   = 0.f;

#define STEP(PP, XIN)                                                        \
    {                                                                        \
        float e_ = ex2(beta - mb);                                           \
        if (h == 0)   sa[PP][tag] = e_;                                      \
        if (tid == 0) s_m[PP] = beta;                                        \
        __syncthreads();                                                     \
        float mbn_ = s_m[PP];                                                \
        const ulonglong2* sp2_ =                                             \
            reinterpret_cast<const ulonglong2*>(&sa[PP][h * 64]);            \
        unsigned long long a0_ = 0ull, a1_ = 0ull, a2_ = 0ull, a3_ = 0ull;   \
        _Pragma("unroll")                                                    \
        for (int j = 0; j < 16; j += 2) {                                    \
            ulonglong2 v0_ = sp2_[j];                                        \
            ulonglong2 v1_ = sp2_[j + 1];                                    \
            FMA2(a0_, er[2 * j],     v0_.x);                                 \
            FMA2(a1_, er[2 * j + 1], v0_.y);                                 \
            FMA2(a2_, er[2 * j + 2], v1_.x);                                 \
            FMA2(a3_, er[2 * j + 3], v1_.y);                                 \
        }                                                                    \
        unsigned long long s01_, s23_, s_;                                   \
        ADD2(s01_, a0_, a1_); ADD2(s23_, a2_, a3_); ADD2(s_, s01_, s23_);    \
        float part_ = hsum2(s_);                                             \
        part_ += __shfl_xor_sync(0xffffffffu, part_, 1);                     \
        beta = (XIN) + mb + lg2(part_);                                      \
        mb = mbn_;                                                           \
    }

    int t = 0;
    const int full = (len / PFD) * PFD;
    for (; t < full; t += PFD) {
#pragma unroll
        for (int d = 0; d < PFD; d++) {
            float cur = xr[d];
            int pf = min(t + d + PFD, len - 1);
            xr[d] = __ldg(xb + (size_t)pf * T_ + tag) * L2E;   // 8 steps ahead
            STEP(d & 1, cur);
        }
    }
    // tail (< PFD steps); parity (full+d)&1 == d&1 since full is even
#pragma unroll
    for (int d = 0; d < PFD - 1; d++) {
        if (t < len) { STEP(d & 1, xr[d]); t++; }
    }
#undef STEP

    // ---- fwd = LSE_i(beta_i + trans[END,i]*L2E) ----
    float v = (h == 0) ? (beta + __ldg(trans + END_ID * T_ + tag) * L2E) : -3.0e38f;
    float mx = warp_max(v);
    __syncthreads();
    if (lane == 0) s_red[w] = mx;
    __syncthreads();
    mx = s_red[0];
#pragma unroll
    for (int k = 1; k < 8; k++) mx = fmaxf(mx, s_red[k]);
    float e2 = (h == 0) ? ex2(v - mx) : 0.f;
    float se = warp_sum(e2);
    __syncthreads();
    if (lane == 0) s_red[w] = se;
    __syncthreads();
    float tot = 0.f;
#pragma unroll
    for (int k = 0; k < 8; k++) tot += s_red[k];
    float fwd = (mx + lg2(tot)) * LN2;

    // ---- gold path score ----
    const int* tb = tags + b * S_;
    float gs = 0.f;
    for (int u = tid; u < len; u += 256) {
        int tn = tb[u + 1];
        int tc = tb[u];
        gs += xb[(size_t)u * T_ + tn] + __ldg(trans + tn * T_ + tc);
    }
    gs = warp_sum(gs);
    __syncthreads();
    if (lane == 0) s_red[w] = gs;
    __syncthreads();
    if (tid == 0) {
        float gtot = 0.f;
#pragma unroll
        for (int k = 0; k < 8; k++) gtot += s_red[k];
        gtot += __ldg(trans + END_ID * T_ + tb[len]);
        g_diff[b] = fwd - gtot;
    }

    // ---- fused finalize: last CTA computes the mean ----
    __syncthreads();
    if (tid == 0) {
        __threadfence();
        int vdone = atomicAdd(&g_done, 1);
        s_last = (vdone == (int)gridDim.x - 1);
    }
    __syncthreads();
    if (s_last) {
        __threadfence();
        float tsum = g_diff[tid] + g_diff[tid + 256];
        tsum = warp_sum(tsum);
        __syncthreads();
        if (lane == 0) s_red[w] = tsum;
        __syncthreads();
        if (tid == 0) {
            float total = 0.f;
#pragma unroll
            for (int k = 0; k < 8; k++) total += s_red[k];
            out[0] = total * (1.0f / B_);
            g_done = 0;   // reset for next graph replay
        }
    }
}

extern "C" void kernel_launch(void* const* d_in, const int* in_sizes, int n_in,
                              void* d_out, int out_size) {
    const float* x     = (const float*)d_in[0];
    const int*   tags  = (const int*)d_in[1];
    const float* mask  = (const float*)d_in[2];
    const float* trans = (const float*)d_in[3];
    crf_kernel<<<B_, 256>>>(x, tags, mask, trans, (float*)d_out);
}

// round 4
// speedup vs baseline: 1.5556x; 1.5060x over previous
#include <cuda_runtime.h>

#define B_ 512
#define S_ 512
#define T_ 128
#define NEGV (-10000.0f)
#define END_ID 1
#define L2E 1.4426950408889634f
#define LN2 0.6931471805599453f
#define PFD 8
#define NCTA 296

__device__ float g_diff[B_];
__device__ int g_next = 0;
__device__ int g_done = 0;

static __device__ __forceinline__ float ex2(float x) {
    float r; asm("ex2.approx.f32 %0, %1;" : "=f"(r) : "f"(x)); return r;
}
static __device__ __forceinline__ float lg2(float x) {
    float r; asm("lg2.approx.f32 %0, %1;" : "=f"(r) : "f"(x)); return r;
}
static __device__ __forceinline__ unsigned long long pack2(float lo, float hi) {
    unsigned long long r;
    asm("mov.b64 %0, {%1, %2};" : "=l"(r) : "r"(__float_as_uint(lo)), "r"(__float_as_uint(hi)));
    return r;
}
static __device__ __forceinline__ float hsum2(unsigned long long v) {
    unsigned int lo, hi;
    asm("mov.b64 {%0, %1}, %2;" : "=r"(lo), "=r"(hi) : "l"(v));
    return __uint_as_float(lo) + __uint_as_float(hi);
}
#define FMA2(acc, e, a) asm("fma.rn.f32x2 %0, %1, %2, %0;" : "+l"(acc) : "l"(e), "l"(a))
#define ADD2(o, a, b)   asm("add.rn.f32x2 %0, %1, %2;" : "=l"(o) : "l"(a), "l"(b))

static __device__ __forceinline__ float warp_sum(float v) {
#pragma unroll
    for (int o = 16; o; o >>= 1) v += __shfl_xor_sync(0xffffffffu, v, o);
    return v;
}
static __device__ __forceinline__ float warp_max(float v) {
#pragma unroll
    for (int o = 16; o; o >>= 1) v = fmaxf(v, __shfl_xor_sync(0xffffffffu, v, o));
    return v;
}

// 256 threads. Warp w: half h = w&1 (warp-uniform!), tags (w>>1)*32 + lane.
// All shared loads in the hot loop are perfect per-warp broadcasts.
__global__ void __launch_bounds__(256, 2) crf_kernel(
    const float* __restrict__ x,      // [B,S,T]
    const int*   __restrict__ tags,   // [B,S]
    const float* __restrict__ mask,   // [B,S]
    const float* __restrict__ trans,  // [T,T]
    float* __restrict__ out)
{
    const int tid  = threadIdx.x;
    const int lane = tid & 31;
    const int w    = tid >> 5;
    const int grp  = w >> 1;            // 0..3
    const int h    = w & 1;             // warp-uniform half
    const int tag  = grp * 32 + lane;   // 0..127

    __shared__ __align__(16) float sa[2][T_];
    __shared__ float s_part[2 * T_];
    __shared__ float s_m[2];
    __shared__ float s_red[8];
    __shared__ int   s_b;
    __shared__ int   s_last;

#define PBAR() asm volatile("bar.sync %0, 64;" :: "r"(grp + 1) : "memory")

    // ---- E regs once per CTA: exp(trans[tag, h*64 .. h*64+63]) packed ----
    unsigned long long er[32];
    {
        const float4* tr4 = reinterpret_cast<const float4*>(trans + tag * T_ + h * 64);
#pragma unroll
        for (int j = 0; j < 16; j++) {
            float4 v = __ldg(tr4 + j);
            er[2 * j]     = pack2(ex2(v.x * L2E), ex2(v.y * L2E));
            er[2 * j + 1] = pack2(ex2(v.z * L2E), ex2(v.w * L2E));
        }
    }

    // ---- persistent work-stealing over batch elements ----
    for (;;) {
        __syncthreads();                       // protect s_b / s_red reuse
        if (tid == 0) s_b = atomicAdd(&g_next, 1);
        __syncthreads();
        const int b = s_b;
        if (b >= B_) break;

        // length = sum(mask[b,:]) (contiguous prefix)
        float lm = mask[b * S_ + tid] + mask[b * S_ + tid + 256];
        lm = warp_sum(lm);
        if (lane == 0) s_red[w] = lm;
        __syncthreads();
        float lt = 0.f;
#pragma unroll
        for (int k = 0; k < 8; k++) lt += s_red[k];
        const int len = (int)(lt + 0.5f);
        const float* xb = x + (size_t)b * S_ * T_;

        // deep x prefetch ring
        float xr[PFD];
#pragma unroll
        for (int d = 0; d < PFD; d++)
            xr[d] = __ldg(xb + (size_t)min(d, len - 1) * T_ + tag) * L2E;

        float beta = (tag == 0) ? 0.f : NEGV * L2E;   // START_ID = 0
        float mb   = 0.f;

#define STEP(PP, XIN)                                                        \
    {                                                                        \
        float e_ = ex2(beta - mb);                                           \
        if (h == 0)   sa[PP][tag] = e_;                                      \
        if (tid == 0) s_m[PP] = beta;                                        \
        __syncthreads();                                                     \
        float mbn_ = s_m[PP];                                                \
        const ulonglong2* sp2_ =                                             \
            reinterpret_cast<const ulonglong2*>(&sa[PP][h * 64]);            \
        unsigned long long a0_ = 0ull, a1_ = 0ull, a2_ = 0ull, a3_ = 0ull;   \
        _Pragma("unroll")                                                    \
        for (int j = 0; j < 16; j += 2) {                                    \
            ulonglong2 v0_ = sp2_[j];                                        \
            ulonglong2 v1_ = sp2_[j + 1];                                    \
            FMA2(a0_, er[2 * j],     v0_.x);                                 \
            FMA2(a1_, er[2 * j + 1], v0_.y);                                 \
            FMA2(a2_, er[2 * j + 2], v1_.x);                                 \
            FMA2(a3_, er[2 * j + 3], v1_.y);                                 \
        }                                                                    \
        unsigned long long s01_, s23_, s_;                                   \
        ADD2(s01_, a0_, a1_); ADD2(s23_, a2_, a3_); ADD2(s_, s01_, s23_);    \
        s_part[tag * 2 + h] = hsum2(s_);                                     \
        PBAR();                                                              \
        float2 pq_ = *reinterpret_cast<const float2*>(&s_part[tag * 2]);     \
        beta = (XIN) + mb + lg2(pq_.x + pq_.y);                              \
        mb = mbn_;                                                           \
    }

        int t = 0;
        const int full = (len / PFD) * PFD;
        for (; t < full; t += PFD) {
#pragma unroll
            for (int d = 0; d < PFD; d++) {
                float cur = xr[d];
                int pf = min(t + d + PFD, len - 1);
                xr[d] = __ldg(xb + (size_t)pf * T_ + tag) * L2E;
                STEP(d & 1, cur);
            }
        }
#pragma unroll
        for (int d = 0; d < PFD - 1; d++) {
            if (t < len) { STEP(d & 1, xr[d]); t++; }
        }
#undef STEP

        // ---- fwd = LSE_i(beta_i + trans[END,i]*L2E) ----
        float v = (h == 0) ? (beta + __ldg(trans + END_ID * T_ + tag) * L2E)
                           : -3.0e38f;
        float mx = warp_max(v);
        __syncthreads();
        if (lane == 0) s_red[w] = mx;
        __syncthreads();
        mx = s_red[0];
#pragma unroll
        for (int k = 1; k < 8; k++) mx = fmaxf(mx, s_red[k]);
        float e2 = (h == 0) ? ex2(v - mx) : 0.f;
        float se = warp_sum(e2);
        __syncthreads();
        if (lane == 0) s_red[w] = se;
        __syncthreads();
        float tot = 0.f;
#pragma unroll
        for (int k = 0; k < 8; k++) tot += s_red[k];
        float fwd = (mx + lg2(tot)) * LN2;

        // ---- gold path score ----
        const int* tb = tags + b * S_;
        float gs = 0.f;
        for (int u = tid; u < len; u += 256) {
            int tn = tb[u + 1];
            int tc = tb[u];
            gs += xb[(size_t)u * T_ + tn] + __ldg(trans + tn * T_ + tc);
        }
        gs = warp_sum(gs);
        __syncthreads();
        if (lane == 0) s_red[w] = gs;
        __syncthreads();
        if (tid == 0) {
            float gtot = 0.f;
#pragma unroll
            for (int k = 0; k < 8; k++) gtot += s_red[k];
            gtot += __ldg(trans + END_ID * T_ + tb[len]);
            g_diff[b] = fwd - gtot;
        }
    }

    // ---- fused finalize: last CTA computes the mean and resets counters ----
    if (tid == 0) {
        __threadfence();
        int vd = atomicAdd(&g_done, 1);
        s_last = (vd == NCTA - 1);
    }
    __syncthreads();
    if (s_last) {
        __threadfence();
        float ts = g_diff[tid] + g_diff[tid + 256];
        ts = warp_sum(ts);
        __syncthreads();
        if (lane == 0) s_red[w] = ts;
        __syncthreads();
        if (tid == 0) {
            float total = 0.f;
#pragma unroll
            for (int k = 0; k < 8; k++) total += s_red[k];
            out[0] = total * (1.0f / B_);
            g_next = 0;     // reset for next graph replay
            g_done = 0;
        }
    }
#undef PBAR
}

extern "C" void kernel_launch(void* const* d_in, const int* in_sizes, int n_in,
                              void* d_out, int out_size) {
    const float* x     = (const float*)d_in[0];
    const int*   tags  = (const int*)d_in[1];
    const float* mask  = (const float*)d_in[2];
    const float* trans = (const float*)d_in[3];
    crf_kernel<<<NCTA, 256>>>(x, tags, mask, trans, (float*)d_out);
}